// round 16
// baseline (speedup 1.0000x reference)
#include <cuda_runtime.h>
#include <cuda_fp16.h>
#include <math.h>
#include <stdint.h>

// ---------------- problem constants ----------------
#define BMOL    512
#define APER    64
#define EUPER   128
#define NATOMS  32768     // BMOL*APER
#define NDIR    131072    // BMOL*2*EUPER
#define NUND    65536     // BMOL*EUPER
#define AFEAT   98
#define BFEAT   111
#define HDIM    256
#define NHEADS  8
#define DKH     32
#define DEPTH   10
#define MLPD    512
#define AOUT    128
#define BOUT    32
#define OUTCOLS 12289     // 128*32 + 64*128 + 1
#define BOND_BLOCK 4096   // EUPER*BOUT

// ---------------- device scratch (allocation-free) ----------------
__device__ float g_h0[(size_t)NDIR * HDIM];
__device__ float g_hA[(size_t)NDIR * HDIM];
__device__ float g_hB[(size_t)NDIR * HDIM];
__device__ float g_asum[(size_t)NATOMS * HDIM];
__device__ float g_afeats[(size_t)NATOMS * HDIM];
__device__ float g_q[(size_t)NATOMS * HDIM];
__device__ float g_k[(size_t)NATOMS * HDIM];
__device__ float g_v[(size_t)NATOMS * HDIM];
__device__ float g_ctx[(size_t)NATOMS * HDIM];
__device__ float g_att[(size_t)NATOMS * HDIM];
__device__ float g_atomf[(size_t)NATOMS * HDIM];
__device__ float g_ahid[(size_t)NATOMS * MLPD];
__device__ float g_bhid[(size_t)NUND * MLPD];
__device__ float g_gvec[(size_t)BMOL * HDIM];
__device__ float g_ghid[(size_t)BMOL * MLPD];
__device__ int   g_t2b[NATOMS * 4];
__device__ int   g_cnt[NATOMS];

// split-weight scratch (fp16): 2 planes per weight, K-major (transposed)
#define OFF_WI     0
#define OFF_WH     65536        // + 2*256*128
#define OFF_WO     196608       // + 2*256*256
#define OFF_WQ     393216       // + 2*256*384
#define OFF_WK     524288
#define OFF_WV     655360
#define OFF_WATTN  786432
#define OFF_VVVC   917504       // + 2*256*256 (wattn)
#define OFF_A1     1179648      // + 2*256*512 (vvvc)
#define OFF_B1     1441792      // + 2*2*256*256 (A1)
#define BPREP_TOTAL 1966080     // + 2*2*256*512 (B1)
__device__ __half g_bprep[BPREP_TOTAL];

// ---------------- helpers ----------------
__device__ __forceinline__ uint32_t smem_u32(const void* p) {
    uint32_t a;
    asm("{ .reg .u64 t; cvta.to.shared.u64 t, %1; cvt.u32.u64 %0, t; }" : "=r"(a) : "l"(p));
    return a;
}

__device__ __forceinline__ void ldsm4(uint32_t* r, uint32_t addr) {
    asm volatile("ldmatrix.sync.aligned.m8n8.x4.shared.b16 {%0,%1,%2,%3}, [%4];"
        : "=r"(r[0]), "=r"(r[1]), "=r"(r[2]), "=r"(r[3]) : "r"(addr));
}

__device__ __forceinline__ void mma16816(float* d, const uint32_t* a, uint32_t b0, uint32_t b1) {
    asm volatile("mma.sync.aligned.m16n8k16.row.col.f32.f16.f16.f32 "
        "{%0,%1,%2,%3},{%4,%5,%6,%7},{%8,%9},{%0,%1,%2,%3};"
        : "+f"(d[0]), "+f"(d[1]), "+f"(d[2]), "+f"(d[3])
        : "r"(a[0]), "r"(a[1]), "r"(a[2]), "r"(a[3]), "r"(b0), "r"(b1));
}

#define CP_ASYNC16(dst, src) \
    asm volatile("cp.async.cg.shared.global [%0], [%1], 16;" :: "r"(dst), "l"(src))
#define CP_COMMIT()  asm volatile("cp.async.commit_group;" ::: "memory")
#define CP_WAIT0()   asm volatile("cp.async.wait_group 0;" ::: "memory")

__device__ __forceinline__ void split2(float v, __half& o0, __half& o1) {
    o0 = __float2half_rn(v);
    float r1 = v - __half2float(o0);
    o1 = __float2half_rn(r1);
}

// ---------------- weight prep: split + transpose into K-major fp16 planes ----------------
__global__ void prep_normal_k(const float* __restrict__ W, int Kw, int Nw, int Kpad,
                              __half* __restrict__ out) {
    int ntiles = Nw >> 8;
    int total = ntiles * 256 * Kpad;
    int idx = blockIdx.x * blockDim.x + threadIdx.x;
    if (idx >= total) return;
    int k = idx % Kpad;
    int nr = idx / Kpad;
    float v = (k < Kw) ? W[(size_t)k * Nw + nr] : 0.f;
    __half p0, p1; split2(v, p0, p1);
    size_t plane = (size_t)total;
    size_t o = (size_t)nr * Kpad + k;
    out[o] = p0; out[plane + o] = p1;
}

__global__ void prep_vvvc_k(const float* __restrict__ Wvv, const float* __restrict__ Wvc,
                            __half* __restrict__ out) {
    int idx = blockIdx.x * blockDim.x + threadIdx.x;   // 256*512
    if (idx >= 256 * 512) return;
    int k = idx & 511, n = idx >> 9;
    float v = (k < 256) ? Wvv[(size_t)n * 256 + k] : Wvc[(size_t)n * 256 + (k - 256)];
    __half p0, p1; split2(v, p0, p1);
    size_t plane = 256 * 512;
    size_t o = (size_t)n * 512 + k;
    out[o] = p0; out[plane + o] = p1;
}

// ---------------- inverse index build (deterministic after sort) ----------------
__global__ void inv_zero_k() {
    int i = blockIdx.x * blockDim.x + threadIdx.x;
    if (i < NATOMS) g_cnt[i] = 0;
}
__global__ void inv_build_k(const int* __restrict__ b2t) {
    int e = blockIdx.x * blockDim.x + threadIdx.x;
    if (e < NDIR) {
        int a = b2t[e];
        int s = atomicAdd(&g_cnt[a], 1);
        if (s < 4) g_t2b[a * 4 + s] = e;
    }
}
__global__ void inv_sort_k() {
    int a = blockIdx.x * blockDim.x + threadIdx.x;
    if (a < NATOMS) {
        int* p = &g_t2b[a * 4];
        int e0 = p[0], e1 = p[1], e2 = p[2], e3 = p[3], t;
        if (e0 > e1) { t = e0; e0 = e1; e1 = t; }
        if (e2 > e3) { t = e2; e2 = e3; e3 = t; }
        if (e0 > e2) { t = e0; e0 = e2; e2 = t; }
        if (e1 > e3) { t = e1; e1 = e3; e3 = t; }
        if (e1 > e2) { t = e1; e1 = e2; e2 = t; }
        p[0] = e0; p[1] = e1; p[2] = e2; p[3] = e3;
    }
}

// ---------------- segment sum ----------------
__global__ void segsum_k(const float* __restrict__ h, float* __restrict__ out) {
    int idx = blockIdx.x * blockDim.x + threadIdx.x;   // NATOMS * 64 float4
    int a = idx >> 6;
    int c4 = idx & 63;
    int4 e = *reinterpret_cast<const int4*>(&g_t2b[a * 4]);
    const float4* h4 = reinterpret_cast<const float4*>(h);
    float4 s0 = h4[(size_t)e.x * 64 + c4];
    float4 s1 = h4[(size_t)e.y * 64 + c4];
    float4 s2 = h4[(size_t)e.z * 64 + c4];
    float4 s3 = h4[(size_t)e.w * 64 + c4];
    float4 r;
    r.x = (s0.x + s1.x) + (s2.x + s3.x);
    r.y = (s0.y + s1.y) + (s2.y + s3.y);
    r.z = (s0.z + s1.z) + (s2.z + s3.z);
    r.w = (s0.w + s1.w) + (s2.w + s3.w);
    reinterpret_cast<float4*>(out)[idx] = r;
}

// ============================================================================
// mma.sync fp16 GEMM: CTA tile 128x256, 8 warps (64x64 each), 3-term 2-way
// fp16 split emulation of fp32, double-buffered software pipeline:
//   issue cp.async B(c+1) + LDG A(c+1) -> MMA(c) -> split/STS A(c+1) -> sync
// AMODE 0: A[row*lda + k]                           (k<K else 0)
// AMODE 1: X1[I1[row]*256 + k] - X2[I2[row]*256 + k]
// AMODE 2: k<98 ? X1[row*98+k] : X2[row*256+(k-98)] (k<K else 0)
// AMODE 3: k<256 ? X1[row*256+k] : X2[row*256+(k-256)]
// AMODE 4: X1[I1[2*row + (k>=256)]*256 + (k&255)]
// ============================================================================
#define AS_STRIDE 144u            // 64 fp16 + 8 pad = 144 bytes/row
#define APLANE    18432u          // 128 rows * 144 B
#define BPLANE    36864u          // 256 rows * 144 B
#define ABUF      (2 * APLANE)    // one A buffer: 2 planes
#define BBUF      (2 * BPLANE)    // one B buffer: 2 planes
#define SMEM_DYN  (2 * (2 * 18432) + 2 * (2 * 36864))   // 216 KB

template<int AMODE, bool BIAS, bool RELU, bool ADDC>
__global__ __launch_bounds__(256, 1)
void tgemm_k(const float* __restrict__ A, int lda,
             const __half* __restrict__ Bprep, int ntiles256,
             const float* __restrict__ bias, const float* __restrict__ Cadd,
             float* __restrict__ C, int Nfull, int K, int Kpad,
             const float* __restrict__ X1, const float* __restrict__ X2,
             const int* __restrict__ I1, const int* __restrict__ I2)
{
    extern __shared__ char sm[];
    const int tid = threadIdx.x;
    const int wid = tid >> 5;
    const int lane = tid & 31;
    const int wm = wid >> 2;      // 0..1  (m block of 64)
    const int wn = wid & 3;       // 0..3  (n block of 64)
    const int rowBase = blockIdx.x * 128;
    const int tileY = blockIdx.y;
    const int colBase = tileY * 256;

    __half* ap = (__half*)sm;                 // 2 buffers x 2 planes A
    const uint32_t aBase = smem_u32(sm);
    const uint32_t bBase = aBase + 2 * ABUF;  // 2 buffers x 2 planes B

    // ldmatrix lane-address offsets (bytes, within a plane; + ks*32 per k16)
    const int lm16 = lane & 15, lh = lane >> 4;
    uint32_t aoffs[4];
    #pragma unroll
    for (int mi = 0; mi < 4; mi++)
        aoffs[mi] = (uint32_t)((wm * 64 + mi * 16 + lm16) * AS_STRIDE + lh * 16);
    uint32_t boffs[4];
    #pragma unroll
    for (int njp = 0; njp < 4; njp++)
        boffs[njp] = (uint32_t)((wn * 64 + njp * 16 + (lane & 7) + ((lane >> 4) << 3)) * AS_STRIDE
                                + ((lane >> 3) & 1) * 16);

    float acc[4][8][4];
    #pragma unroll
    for (int mi = 0; mi < 4; mi++)
        #pragma unroll
        for (int nj = 0; nj < 8; nj++)
            #pragma unroll
            for (int u = 0; u < 4; u++) acc[mi][nj][u] = 0.f;

    const int kk = tid & 63;     // A-fill column within chunk
    const int r0 = tid >> 6;     // A-fill base row (step 4)
    const int nchunks = Kpad >> 6;

    // ---- pipeline helpers (inlined via lambdas) ----
    auto issueB = [&](int c, int buf) {
        #pragma unroll
        for (int t = 0; t < 16; t++) {
            int id = t * 256 + tid;          // 0..4095
            int p = id >> 11;                // plane
            int rem = id & 2047;
            int n = rem >> 3;                // n row 0..255
            int u = rem & 7;                 // 16B chunk in k
            const __half* src = Bprep +
                ((size_t)((p * ntiles256 + tileY) * 256 + n)) * Kpad + c * 64 + u * 8;
            uint32_t dst = bBase + (uint32_t)buf * BBUF + (uint32_t)p * BPLANE
                         + (uint32_t)n * AS_STRIDE + u * 16;
            CP_ASYNC16(dst, src);
        }
        CP_COMMIT();
    };
    auto fetchA = [&](int c, float* av) {
        const int k = c * 64 + kk;
        #pragma unroll
        for (int v = 0; v < 32; v++) {
            int grow = rowBase + r0 + (v << 2);
            float val = 0.f;
            if (AMODE == 0) {
                if (k < K) val = A[(size_t)grow * lda + k];
            } else if (AMODE == 1) {
                val = X1[(size_t)I1[grow] * HDIM + k] - X2[(size_t)I2[grow] * HDIM + k];
            } else if (AMODE == 2) {
                if (k < AFEAT)      val = X1[(size_t)grow * AFEAT + k];
                else if (k < K)     val = X2[(size_t)grow * HDIM + (k - AFEAT)];
            } else if (AMODE == 3) {
                val = (k < HDIM) ? X1[(size_t)grow * HDIM + k]
                                 : X2[(size_t)grow * HDIM + (k - HDIM)];
            } else {
                val = X1[(size_t)I1[2 * grow + (k >= HDIM)] * HDIM + (k & 255)];
            }
            av[v] = val;
        }
    };
    auto storeA = [&](const float* av, int buf) {
        #pragma unroll
        for (int v = 0; v < 32; v++) {
            int r = r0 + (v << 2);
            __half p0, p1; split2(av[v], p0, p1);
            uint32_t so = (uint32_t)buf * (ABUF / 2) + (uint32_t)r * (AS_STRIDE / 2) + kk;
            ap[so] = p0;
            ap[so + APLANE / 2] = p1;
        }
    };

    // ---- prologue: fill buffer 0 ----
    float av[32];
    issueB(0, 0);
    fetchA(0, av);
    storeA(av, 0);
    CP_WAIT0();
    __syncthreads();

    const int pa[3] = {0, 0, 1};
    const int pb[3] = {0, 1, 0};

    for (int c = 0; c < nchunks; c++) {
        const int cur = c & 1, nxt = cur ^ 1;
        const bool hasNext = (c + 1 < nchunks);
        if (hasNext) {
            issueB(c + 1, nxt);
            fetchA(c + 1, av);       // LDGs in flight across the MMA block
        }

        #pragma unroll
        for (int j = 0; j < 3; j++) {
            uint32_t ab = aBase + (uint32_t)cur * ABUF + (uint32_t)pa[j] * APLANE;
            uint32_t bb = bBase + (uint32_t)cur * BBUF + (uint32_t)pb[j] * BPLANE;
            #pragma unroll
            for (int ks = 0; ks < 4; ks++) {
                uint32_t af[4][4];
                #pragma unroll
                for (int mi = 0; mi < 4; mi++) ldsm4(af[mi], ab + aoffs[mi] + ks * 32);
                uint32_t bf[4][4];
                #pragma unroll
                for (int njp = 0; njp < 4; njp++) ldsm4(bf[njp], bb + boffs[njp] + ks * 32);
                #pragma unroll
                for (int mi = 0; mi < 4; mi++) {
                    #pragma unroll
                    for (int njp = 0; njp < 4; njp++) {
                        mma16816(acc[mi][2 * njp],     af[mi], bf[njp][0], bf[njp][1]);
                        mma16816(acc[mi][2 * njp + 1], af[mi], bf[njp][2], bf[njp][3]);
                    }
                }
            }
        }

        if (hasNext) {
            storeA(av, nxt);
            CP_WAIT0();
        }
        __syncthreads();
    }

    // ---- epilogue: fused bias / C-add / relu, direct float2 stores ----
    #pragma unroll
    for (int mi = 0; mi < 4; mi++) {
        int r0g = rowBase + wm * 64 + mi * 16 + (lane >> 2);
        int r1g = r0g + 8;
        #pragma unroll
        for (int nj = 0; nj < 8; nj++) {
            int col = colBase + wn * 64 + nj * 8 + (lane & 3) * 2;
            float v0 = acc[mi][nj][0], v1 = acc[mi][nj][1];
            float v2 = acc[mi][nj][2], v3 = acc[mi][nj][3];
            if (BIAS) {
                float2 b2v = *(const float2*)&bias[col];
                v0 += b2v.x; v1 += b2v.y; v2 += b2v.x; v3 += b2v.y;
            }
            if (ADDC) {
                float2 c0 = *(const float2*)&Cadd[(size_t)r0g * Nfull + col];
                float2 c1 = *(const float2*)&Cadd[(size_t)r1g * Nfull + col];
                v0 += c0.x; v1 += c0.y; v2 += c1.x; v3 += c1.y;
            }
            if (RELU) {
                v0 = fmaxf(v0, 0.f); v1 = fmaxf(v1, 0.f);
                v2 = fmaxf(v2, 0.f); v3 = fmaxf(v3, 0.f);
            }
            float2 w0 = make_float2(v0, v1), w1 = make_float2(v2, v3);
            *(float2*)&C[(size_t)r0g * Nfull + col] = w0;
            *(float2*)&C[(size_t)r1g * Nfull + col] = w1;
        }
    }
}

template<int AM, bool BI, bool RE, bool AD>
static inline void tgemm(const float* A, int lda, const __half* Bp,
                         const float* bias, const float* Cadd, float* C,
                         int M, int Nfull, int K, int Kpad,
                         const float* X1 = nullptr, const float* X2 = nullptr,
                         const int* I1 = nullptr, const int* I2 = nullptr) {
    cudaFuncSetAttribute(tgemm_k<AM, BI, RE, AD>,
                         cudaFuncAttributeMaxDynamicSharedMemorySize, SMEM_DYN);
    dim3 grid(M / 128, Nfull / 256);
    tgemm_k<AM, BI, RE, AD><<<grid, 256, SMEM_DYN>>>(
        A, lda, Bp, Nfull / 256, bias, Cadd, C, Nfull, K, Kpad, X1, X2, I1, I2);
}

// ---------------- fp32 SIMT GEMM (small heads only) ----------------
template<bool BIAS, bool RELU, int OUTMODE>
__global__ __launch_bounds__(256, 2)
void gemm_k(const float* __restrict__ A, int lda,
            const float* __restrict__ B,
            const float* __restrict__ bias,
            float* __restrict__ C,
            int M, int N, int K)
{
    __shared__ float As[16][128];
    __shared__ float Bs[16][128];

    const int tid = threadIdx.x;
    const int ty = tid >> 4, tx = tid & 15;
    const int rowBase = blockIdx.x * 128;
    const int colBase = blockIdx.y * 128;
    const int lm = tid & 127;
    const int lk = tid >> 7;
    const int arow = rowBase + lm;
    const float* pA = A + (size_t)arow * lda;

    float acc[8][8];
    #pragma unroll
    for (int i = 0; i < 8; i++)
        #pragma unroll
        for (int j = 0; j < 8; j++) acc[i][j] = 0.f;

    for (int k0 = 0; k0 < K; k0 += 16) {
        #pragma unroll
        for (int jj = 0; jj < 8; jj++) {
            int kk2 = lk + 2 * jj;
            int kg = k0 + kk2;
            As[kk2][lm] = (kg < K) ? pA[kg] : 0.f;
        }
        {
            int ng = colBase + lm;
            #pragma unroll
            for (int jj = 0; jj < 8; jj++) {
                int kk2 = lk + 2 * jj;
                int kg = k0 + kk2;
                float val = 0.f;
                if (kg < K && ng < N) val = B[(size_t)kg * N + ng];
                Bs[kk2][lm] = val;
            }
        }
        __syncthreads();
        #pragma unroll
        for (int kk2 = 0; kk2 < 16; kk2++) {
            const float4* apx = reinterpret_cast<const float4*>(&As[kk2][ty * 8]);
            const float4* bpx = reinterpret_cast<const float4*>(&Bs[kk2][tx * 8]);
            float4 a0 = apx[0], a1 = apx[1];
            float4 b0 = bpx[0], b1 = bpx[1];
            float a[8], b[8];
            a[0] = a0.x; a[1] = a0.y; a[2] = a0.z; a[3] = a0.w;
            a[4] = a1.x; a[5] = a1.y; a[6] = a1.z; a[7] = a1.w;
            b[0] = b0.x; b[1] = b0.y; b[2] = b0.z; b[3] = b0.w;
            b[4] = b1.x; b[5] = b1.y; b[6] = b1.z; b[7] = b1.w;
            #pragma unroll
            for (int i = 0; i < 8; i++)
                #pragma unroll
                for (int j = 0; j < 8; j++)
                    acc[i][j] += a[i] * b[j];
        }
        __syncthreads();
    }

    #pragma unroll
    for (int i = 0; i < 8; i++) {
        int r = rowBase + ty * 8 + i;
        #pragma unroll
        for (int j = 0; j < 8; j++) {
            int n = colBase + tx * 8 + j;
            float val = acc[i][j];
            if (BIAS) val += (n < N) ? bias[n] : 0.f;
            if (RELU) val = fmaxf(val, 0.f);
            if (OUTMODE == 0) {
                C[(size_t)r * N + n] = val;
            } else if (n < N) {
                size_t o;
                if (OUTMODE == 1)
                    o = (size_t)(r >> 6) * OUTCOLS + BOND_BLOCK + (size_t)(r & 63) * AOUT + n;
                else
                    o = (size_t)(r >> 7) * OUTCOLS + (size_t)(r & 127) * BOUT + n;
                C[o] = val;
            }
        }
    }
}

template<bool BI, bool RE, int OM>
static inline void gemm32(const float* A, int lda, const float* B, const float* bias,
                          float* C, int M, int N, int K) {
    dim3 grid(M / 128, (N + 127) / 128);
    gemm_k<BI, RE, OM><<<grid, 256>>>(A, lda, B, bias, C, M, N, K);
}

// ---------------- per-(molecule, head) attention ----------------
__global__ __launch_bounds__(64)
void attn_k(const float* __restrict__ q, const float* __restrict__ k,
            const float* __restrict__ v, float* __restrict__ ctx)
{
    __shared__ float Qs[64][32], Ks[64][32], Vs[64][32];
    __shared__ float Ss[64][65];

    int mol  = blockIdx.x >> 3;
    int head = blockIdx.x & 7;
    int t = threadIdx.x;
    size_t rbase = ((size_t)mol * APER + t) * HDIM + head * DKH;

    #pragma unroll
    for (int c = 0; c < 32; c += 4) {
        *(float4*)&Qs[t][c] = *(const float4*)&q[rbase + c];
        *(float4*)&Ks[t][c] = *(const float4*)&k[rbase + c];
        *(float4*)&Vs[t][c] = *(const float4*)&v[rbase + c];
    }
    __syncthreads();

    float qr[32];
    #pragma unroll
    for (int c = 0; c < 32; c++) qr[c] = Qs[t][c];

    const float scale = 0.17677669529663687f;
    float mx = -1e30f;
    for (int j = 0; j < 64; j++) {
        float d = 0.f;
        #pragma unroll
        for (int c = 0; c < 32; c++) d += qr[c] * Ks[j][c];
        d *= scale;
        Ss[t][j] = d;
        mx = fmaxf(mx, d);
    }
    float sum = 0.f;
    for (int j = 0; j < 64; j++) {
        float e = expf(Ss[t][j] - mx);
        Ss[t][j] = e;
        sum += e;
    }
    float inv = 1.f / sum;

    float o[32];
    #pragma unroll
    for (int c = 0; c < 32; c++) o[c] = 0.f;
    for (int j = 0; j < 64; j++) {
        float sj = Ss[t][j];
        #pragma unroll
        for (int c = 0; c < 32; c++) o[c] += sj * Vs[j][c];
    }
    #pragma unroll
    for (int c = 0; c < 32; c += 4) {
        float4 w = make_float4(o[c] * inv, o[c + 1] * inv, o[c + 2] * inv, o[c + 3] * inv);
        *(float4*)&ctx[rbase + c] = w;
    }
}

// ---------------- graph vector + final graph projection ----------------
__global__ void gvec_k(const float* __restrict__ af, float* __restrict__ gv) {
    int mol = blockIdx.x;
    int c = threadIdx.x;
    const float* p = af + (size_t)mol * APER * HDIM + c;
    float s = 0.f;
    #pragma unroll 8
    for (int i = 0; i < APER; i++) s += p[(size_t)i * HDIM];
    gv[mol * HDIM + c] = s;
}

__global__ void gout_k(const float* __restrict__ ghid, const float* __restrict__ G2,
                       const float* __restrict__ g2, float* __restrict__ out) {
    int m = blockIdx.x * blockDim.x + threadIdx.x;
    if (m < BMOL) {
        float s = g2[0];
        const float* p = ghid + (size_t)m * MLPD;
        #pragma unroll 8
        for (int kk = 0; kk < MLPD; kk++) s += p[kk] * G2[kk];
        out[(size_t)m * OUTCOLS + (OUTCOLS - 1)] = s;
    }
}

// ---------------- launcher ----------------
extern "C" void kernel_launch(void* const* d_in, const int* in_sizes, int n_in,
                              void* d_out, int out_size) {
    (void)in_sizes; (void)n_in; (void)out_size;

    const float* f_atoms    = (const float*)d_in[0];
    const float* f_bonds    = (const float*)d_in[1];
    const float* prev_hid   = (const float*)d_in[2];
    const int*   b2a        = (const int*)d_in[3];
    const int*   b2t        = (const int*)d_in[4];
    const int*   b2rev      = (const int*)d_in[5];
    const int*   bond_pairs = (const int*)d_in[6];
    const float* W_i   = (const float*)d_in[7];
    const float* W_h   = (const float*)d_in[8];
    const float* W_o   = (const float*)d_in[9];
    const float* b_o   = (const float*)d_in[10];
    const float* Wq    = (const float*)d_in[11];
    const float* Wk    = (const float*)d_in[12];
    const float* Wv    = (const float*)d_in[13];
    const float* Wattn = (const float*)d_in[14];
    const float* W_vv  = (const float*)d_in[15];
    const float* W_vc  = (const float*)d_in[16];
    const float* A1    = (const float*)d_in[17];
    const float* a1    = (const float*)d_in[18];
    const float* A2    = (const float*)d_in[19];
    const float* a2    = (const float*)d_in[20];
    const float* B1    = (const float*)d_in[21];
    const float* b1    = (const float*)d_in[22];
    const float* B2    = (const float*)d_in[23];
    const float* b2b   = (const float*)d_in[24];
    const float* G1    = (const float*)d_in[25];
    const float* g1    = (const float*)d_in[26];
    const float* G2    = (const float*)d_in[27];
    const float* g2    = (const float*)d_in[28];
    float* out = (float*)d_out;

    float *h0, *hA, *hB, *asum, *afeats, *qp, *kp, *vp, *ctx, *att, *atomf;
    float *ahid, *bhid, *gvec, *ghid;
    __half* bprep;
    void* p;
    cudaGetSymbolAddress(&p, g_h0);     h0     = (float*)p;
    cudaGetSymbolAddress(&p, g_hA);     hA     = (float*)p;
    cudaGetSymbolAddress(&p, g_hB);     hB     = (float*)p;
    cudaGetSymbolAddress(&p, g_asum);   asum   = (float*)p;
    cudaGetSymbolAddress(&p, g_afeats); afeats = (float*)p;
    cudaGetSymbolAddress(&p, g_q);      qp     = (float*)p;
    cudaGetSymbolAddress(&p, g_k);      kp     = (float*)p;
    cudaGetSymbolAddress(&p, g_v);      vp     = (float*)p;
    cudaGetSymbolAddress(&p, g_ctx);    ctx    = (float*)p;
    cudaGetSymbolAddress(&p, g_att);    att    = (float*)p;
    cudaGetSymbolAddress(&p, g_atomf);  atomf  = (float*)p;
    cudaGetSymbolAddress(&p, g_ahid);   ahid   = (float*)p;
    cudaGetSymbolAddress(&p, g_bhid);   bhid   = (float*)p;
    cudaGetSymbolAddress(&p, g_gvec);   gvec   = (float*)p;
    cudaGetSymbolAddress(&p, g_ghid);   ghid   = (float*)p;
    cudaGetSymbolAddress(&p, g_bprep);  bprep  = (__half*)p;

    // ---- weight split/transpose prep ----
    auto prepN = [&](const float* W, int Kw, int Nw, int Kpad, size_t off) {
        int total = (Nw >> 8) * 256 * Kpad;
        prep_normal_k<<<(total + 255) / 256, 256>>>(W, Kw, Nw, Kpad, bprep + off);
    };
    prepN(W_i,   111, 256, 128, OFF_WI);
    prepN(W_h,   256, 256, 256, OFF_WH);
    prepN(W_o,   354, 256, 384, OFF_WO);
    prepN(Wq,    256, 256, 256, OFF_WQ);
    prepN(Wk,    256, 256, 256, OFF_WK);
    prepN(Wv,    256, 256, 256, OFF_WV);
    prepN(Wattn, 256, 256, 256, OFF_WATTN);
    prep_vvvc_k<<<(256 * 512 + 255) / 256, 256>>>(W_vv, W_vc, bprep + OFF_VVVC);
    prepN(A1,    256, 512, 256, OFF_A1);
    prepN(B1,    512, 512, 512, OFF_B1);

    // ---- inverse edge index ----
    inv_zero_k<<<NATOMS / 256, 256>>>();
    inv_build_k<<<NDIR / 256, 256>>>(b2t);
    inv_sort_k<<<NATOMS / 256, 256>>>();

    // ---- h0 = relu(f_bonds @ W_i) ----
    tgemm<0, false, true, false>(f_bonds, BFEAT, bprep + OFF_WI, nullptr, nullptr,
                                 h0, NDIR, 256, 111, 128);

    // ---- DMPNN loop ----
    const float* hcur = h0;
    for (int it = 0; it < DEPTH - 1; ++it) {
        float* dst = (it & 1) ? hB : hA;
        segsum_k<<<(NATOMS * (HDIM / 4)) / 256, 256>>>(hcur, asum);
        tgemm<1, false, true, true>(nullptr, 0, bprep + OFF_WH, nullptr, h0, dst,
                                    NDIR, 256, 256, 256, asum, hcur, b2a, b2rev);
        hcur = dst;
    }

    // ---- atom features ----
    segsum_k<<<(NATOMS * (HDIM / 4)) / 256, 256>>>(hcur, asum);
    tgemm<2, true, true, false>(nullptr, 0, bprep + OFF_WO, b_o, nullptr, afeats,
                                NATOMS, 256, 354, 384, f_atoms, asum);

    // ---- attention ----
    tgemm<0, false, false, false>(afeats, 256, bprep + OFF_WQ, nullptr, nullptr, qp, NATOMS, 256, 256, 256);
    tgemm<0, false, false, false>(afeats, 256, bprep + OFF_WK, nullptr, nullptr, kp, NATOMS, 256, 256, 256);
    tgemm<0, false, false, false>(afeats, 256, bprep + OFF_WV, nullptr, nullptr, vp, NATOMS, 256, 256, 256);
    attn_k<<<BMOL * NHEADS, 64>>>(qp, kp, vp, ctx);
    tgemm<0, false, false, true>(ctx, 256, bprep + OFF_WATTN, nullptr, afeats, att, NATOMS, 256, 256, 256);

    // ---- atom_feats = relu(prev_hid @ Wvv.T + att @ Wvc.T) (fused concat GEMM) ----
    tgemm<3, false, true, false>(nullptr, 0, bprep + OFF_VVVC, nullptr, nullptr, atomf,
                                 NATOMS, 256, 512, 512, prev_hid, att);

    // ---- atom head ----
    tgemm<0, true, true, false>(atomf, 256, bprep + OFF_A1, a1, nullptr, ahid,
                                NATOMS, 512, 256, 256);
    gemm32<true, false, 1>(ahid, MLPD, A2, a2, out, NATOMS, AOUT, MLPD);

    // ---- bond head ----
    tgemm<4, true, true, false>(nullptr, 0, bprep + OFF_B1, b1, nullptr, bhid,
                                NUND, 512, 512, 512, atomf, nullptr, bond_pairs, nullptr);
    gemm32<true, false, 2>(bhid, MLPD, B2, b2b, out, NUND, BOUT, MLPD);

    // ---- graph head ----
    gvec_k<<<BMOL, HDIM>>>(atomf, gvec);
    gemm32<true, true, 0>(gvec, HDIM, G1, g1, ghid, BMOL, MLPD, HDIM);
    gout_k<<<(BMOL + 255) / 256, 256>>>(ghid, G2, g2, out);
}

// round 17
// speedup vs baseline: 1.1658x; 1.1658x over previous
#include <cuda_runtime.h>
#include <cuda_fp16.h>
#include <math.h>
#include <stdint.h>

// ---------------- problem constants ----------------
#define BMOL    512
#define APER    64
#define EUPER   128
#define NATOMS  32768     // BMOL*APER
#define NDIR    131072    // BMOL*2*EUPER
#define NUND    65536     // BMOL*EUPER
#define AFEAT   98
#define BFEAT   111
#define HDIM    256
#define NHEADS  8
#define DKH     32
#define DEPTH   10
#define MLPD    512
#define AOUT    128
#define BOUT    32
#define OUTCOLS 12289     // 128*32 + 64*128 + 1
#define BOND_BLOCK 4096   // EUPER*BOUT

// ---------------- device scratch (allocation-free) ----------------
__device__ float g_h0[(size_t)NDIR * HDIM];
__device__ float g_hA[(size_t)NDIR * HDIM];
__device__ float g_hB[(size_t)NDIR * HDIM];
__device__ float g_asum[(size_t)NATOMS * HDIM];
__device__ float g_afeats[(size_t)NATOMS * HDIM];
__device__ float g_q[(size_t)NATOMS * HDIM];
__device__ float g_k[(size_t)NATOMS * HDIM];
__device__ float g_v[(size_t)NATOMS * HDIM];
__device__ float g_ctx[(size_t)NATOMS * HDIM];
__device__ float g_att[(size_t)NATOMS * HDIM];
__device__ float g_atomf[(size_t)NATOMS * HDIM];
__device__ float g_ahid[(size_t)NATOMS * MLPD];
__device__ float g_bhid[(size_t)NUND * MLPD];
__device__ float g_gvec[(size_t)BMOL * HDIM];
__device__ float g_ghid[(size_t)BMOL * MLPD];
__device__ int   g_t2b[NATOMS * 4];
__device__ int   g_cnt[NATOMS];

// pre-split A-operand planes (fp16, 2 planes each)
__device__ __half g_msgP[(size_t)2 * NDIR * HDIM];     // DMPNN messages
__device__ __half g_afP[(size_t)2 * NATOMS * HDIM];    // afeats (q/k/v A)
__device__ __half g_atfP[(size_t)2 * NATOMS * HDIM];   // atomf (A1, bond gather)

// split-weight scratch (fp16): 2 planes per weight, K-major (transposed)
#define OFF_WI     0
#define OFF_WH     65536
#define OFF_WO     196608
#define OFF_WQ     393216
#define OFF_WK     524288
#define OFF_WV     655360
#define OFF_WATTN  786432
#define OFF_VVVC   917504
#define OFF_A1     1179648
#define OFF_B1     1441792
#define BPREP_TOTAL 1966080
__device__ __half g_bprep[BPREP_TOTAL];

// ---------------- helpers ----------------
__device__ __forceinline__ uint32_t smem_u32(const void* p) {
    uint32_t a;
    asm("{ .reg .u64 t; cvta.to.shared.u64 t, %1; cvt.u32.u64 %0, t; }" : "=r"(a) : "l"(p));
    return a;
}

__device__ __forceinline__ void ldsm4(uint32_t* r, uint32_t addr) {
    asm volatile("ldmatrix.sync.aligned.m8n8.x4.shared.b16 {%0,%1,%2,%3}, [%4];"
        : "=r"(r[0]), "=r"(r[1]), "=r"(r[2]), "=r"(r[3]) : "r"(addr));
}

__device__ __forceinline__ void mma16816(float* d, const uint32_t* a, uint32_t b0, uint32_t b1) {
    asm volatile("mma.sync.aligned.m16n8k16.row.col.f32.f16.f16.f32 "
        "{%0,%1,%2,%3},{%4,%5,%6,%7},{%8,%9},{%0,%1,%2,%3};"
        : "+f"(d[0]), "+f"(d[1]), "+f"(d[2]), "+f"(d[3])
        : "r"(a[0]), "r"(a[1]), "r"(a[2]), "r"(a[3]), "r"(b0), "r"(b1));
}

#define CP_ASYNC16(dst, src) \
    asm volatile("cp.async.cg.shared.global [%0], [%1], 16;" :: "r"(dst), "l"(src))
#define CP_COMMIT()  asm volatile("cp.async.commit_group;" ::: "memory")
#define CP_WAIT0()   asm volatile("cp.async.wait_group 0;" ::: "memory")

__device__ __forceinline__ void split2(float v, __half& o0, __half& o1) {
    o0 = __float2half_rn(v);
    float r1 = v - __half2float(o0);
    o1 = __float2half_rn(r1);
}

__device__ __forceinline__ uint2 pack4h(__half a, __half b, __half c, __half d) {
    uint2 u;
    u.x = (uint32_t)__half_as_ushort(a) | ((uint32_t)__half_as_ushort(b) << 16);
    u.y = (uint32_t)__half_as_ushort(c) | ((uint32_t)__half_as_ushort(d) << 16);
    return u;
}

// ---------------- weight prep: split + transpose into K-major fp16 planes ----------------
__global__ void prep_normal_k(const float* __restrict__ W, int Kw, int Nw, int Kpad,
                              __half* __restrict__ out) {
    int ntiles = Nw >> 8;
    int total = ntiles * 256 * Kpad;
    int idx = blockIdx.x * blockDim.x + threadIdx.x;
    if (idx >= total) return;
    int k = idx % Kpad;
    int nr = idx / Kpad;
    float v = (k < Kw) ? W[(size_t)k * Nw + nr] : 0.f;
    __half p0, p1; split2(v, p0, p1);
    size_t plane = (size_t)total;
    size_t o = (size_t)nr * Kpad + k;
    out[o] = p0; out[plane + o] = p1;
}

__global__ void prep_vvvc_k(const float* __restrict__ Wvv, const float* __restrict__ Wvc,
                            __half* __restrict__ out) {
    int idx = blockIdx.x * blockDim.x + threadIdx.x;   // 256*512
    if (idx >= 256 * 512) return;
    int k = idx & 511, n = idx >> 9;
    float v = (k < 256) ? Wvv[(size_t)n * 256 + k] : Wvc[(size_t)n * 256 + (k - 256)];
    __half p0, p1; split2(v, p0, p1);
    size_t plane = 256 * 512;
    size_t o = (size_t)n * 512 + k;
    out[o] = p0; out[plane + o] = p1;
}

// ---------------- A-operand plane prep ----------------
// DMPNN message: m[e] = asum[b2a[e]] - h[b2rev[e]], split into 2 fp16 planes
__global__ void amsg_split_k(const float* __restrict__ asum, const float* __restrict__ h,
                             const int* __restrict__ b2a, const int* __restrict__ b2rev,
                             __half* __restrict__ outP) {
    int idx = blockIdx.x * blockDim.x + threadIdx.x;   // NDIR * 64
    int e = idx >> 6, c4 = idx & 63;
    int a = b2a[e], rv = b2rev[e];
    float4 s = ((const float4*)asum)[(size_t)a * 64 + c4];
    float4 r = ((const float4*)h)[(size_t)rv * 64 + c4];
    float v0 = s.x - r.x, v1 = s.y - r.y, v2 = s.z - r.z, v3 = s.w - r.w;
    __half l0, h0_, l1, h1_, l2, h2_, l3, h3_;
    split2(v0, l0, h0_); split2(v1, l1, h1_);
    split2(v2, l2, h2_); split2(v3, l3, h3_);
    size_t o = (size_t)e * 64 + c4;
    ((uint2*)outP)[o] = pack4h(l0, l1, l2, l3);
    ((uint2*)(outP + (size_t)NDIR * HDIM))[o] = pack4h(h0_, h1_, h2_, h3_);
}

// generic fp32 [M x 256] -> 2 fp16 planes
__global__ void split_mat_k(const float* __restrict__ in, __half* __restrict__ outP, int M) {
    int idx = blockIdx.x * blockDim.x + threadIdx.x;   // M * 64
    if (idx >= M * 64) return;
    float4 s = ((const float4*)in)[idx];
    __half l0, h0_, l1, h1_, l2, h2_, l3, h3_;
    split2(s.x, l0, h0_); split2(s.y, l1, h1_);
    split2(s.z, l2, h2_); split2(s.w, l3, h3_);
    ((uint2*)outP)[idx] = pack4h(l0, l1, l2, l3);
    ((uint2*)(outP + (size_t)M * HDIM))[idx] = pack4h(h0_, h1_, h2_, h3_);
}

// ---------------- inverse index build (deterministic after sort) ----------------
__global__ void inv_zero_k() {
    int i = blockIdx.x * blockDim.x + threadIdx.x;
    if (i < NATOMS) g_cnt[i] = 0;
}
__global__ void inv_build_k(const int* __restrict__ b2t) {
    int e = blockIdx.x * blockDim.x + threadIdx.x;
    if (e < NDIR) {
        int a = b2t[e];
        int s = atomicAdd(&g_cnt[a], 1);
        if (s < 4) g_t2b[a * 4 + s] = e;
    }
}
__global__ void inv_sort_k() {
    int a = blockIdx.x * blockDim.x + threadIdx.x;
    if (a < NATOMS) {
        int* p = &g_t2b[a * 4];
        int e0 = p[0], e1 = p[1], e2 = p[2], e3 = p[3], t;
        if (e0 > e1) { t = e0; e0 = e1; e1 = t; }
        if (e2 > e3) { t = e2; e2 = e3; e3 = t; }
        if (e0 > e2) { t = e0; e0 = e2; e2 = t; }
        if (e1 > e3) { t = e1; e1 = e3; e3 = t; }
        if (e1 > e2) { t = e1; e1 = e2; e2 = t; }
        p[0] = e0; p[1] = e1; p[2] = e2; p[3] = e3;
    }
}

// ---------------- segment sum ----------------
__global__ void segsum_k(const float* __restrict__ h, float* __restrict__ out) {
    int idx = blockIdx.x * blockDim.x + threadIdx.x;   // NATOMS * 64 float4
    int a = idx >> 6;
    int c4 = idx & 63;
    int4 e = *reinterpret_cast<const int4*>(&g_t2b[a * 4]);
    const float4* h4 = reinterpret_cast<const float4*>(h);
    float4 s0 = h4[(size_t)e.x * 64 + c4];
    float4 s1 = h4[(size_t)e.y * 64 + c4];
    float4 s2 = h4[(size_t)e.z * 64 + c4];
    float4 s3 = h4[(size_t)e.w * 64 + c4];
    float4 r;
    r.x = (s0.x + s1.x) + (s2.x + s3.x);
    r.y = (s0.y + s1.y) + (s2.y + s3.y);
    r.z = (s0.z + s1.z) + (s2.z + s3.z);
    r.w = (s0.w + s1.w) + (s2.w + s3.w);
    reinterpret_cast<float4*>(out)[idx] = r;
}

// ============================================================================
// mma.sync fp16 GEMM: CTA tile 128x256, 8 warps (64x64 each), 3-term 2-way
// fp16 split emulation of fp32.
// AMODE 0: A[row*lda + k] generated in-kernel     (k<K else 0)
// AMODE 2: k<98 ? X1[row*98+k] : X2[row*256+(k-98)]
// AMODE 3: k<256 ? X1[row*256+k] : X2[row*256+(k-256)]
// AMODE 5: pre-split planes, direct rows   -> full cp.async double-buffer PIPE
// AMODE 6: pre-split planes, bond-pair row gather -> PIPE
// ============================================================================
#define AS_STRIDE 144u            // 64 fp16 + 8 pad = 144 bytes/row
#define APLANE    18432u          // 128 rows * 144 B
#define BPLANE    36864u          // 256 rows * 144 B
#define ABUF      (2 * APLANE)
#define BBUF      (2 * BPLANE)
#define SMEM_PIPE   (2 * (2 * 18432) + 2 * (2 * 36864))   // 216 KB
#define SMEM_SINGLE (2 * 18432 + 2 * 36864)               // 108 KB

template<int AMODE, bool BIAS, bool RELU, bool ADDC>
__global__ __launch_bounds__(256, 1)
void tgemm_k(const float* __restrict__ A, int lda,
             const __half* __restrict__ Bprep, int ntiles256,
             const __half* __restrict__ Aprep, size_t aStride,
             const float* __restrict__ bias, const float* __restrict__ Cadd,
             float* __restrict__ C, int Nfull, int K, int Kpad,
             const float* __restrict__ X1, const float* __restrict__ X2,
             const int* __restrict__ I1, const int* __restrict__ I2)
{
    constexpr bool PIPE = (AMODE >= 5);
    extern __shared__ char sm[];
    const int tid = threadIdx.x;
    const int wid = tid >> 5;
    const int lane = tid & 31;
    const int wm = wid >> 2;
    const int wn = wid & 3;
    const int rowBase = blockIdx.x * 128;
    const int tileY = blockIdx.y;
    const int colBase = tileY * 256;

    __half* ap = (__half*)sm;
    const uint32_t aBase = smem_u32(sm);
    const uint32_t bBase = aBase + (PIPE ? 2 * ABUF : ABUF);

    const int lm16 = lane & 15, lh = lane >> 4;
    uint32_t aoffs[4];
    #pragma unroll
    for (int mi = 0; mi < 4; mi++)
        aoffs[mi] = (uint32_t)((wm * 64 + mi * 16 + lm16) * AS_STRIDE + lh * 16);
    uint32_t boffs[4];
    #pragma unroll
    for (int njp = 0; njp < 4; njp++)
        boffs[njp] = (uint32_t)((wn * 64 + njp * 16 + (lane & 7) + ((lane >> 4) << 3)) * AS_STRIDE
                                + ((lane >> 3) & 1) * 16);

    float acc[4][8][4];
    #pragma unroll
    for (int mi = 0; mi < 4; mi++)
        #pragma unroll
        for (int nj = 0; nj < 8; nj++)
            #pragma unroll
            for (int u = 0; u < 4; u++) acc[mi][nj][u] = 0.f;

    const int kk = tid & 63;
    const int r0 = tid >> 6;
    const int nchunks = Kpad >> 6;

    auto issueB = [&](int c, int buf) {
        #pragma unroll
        for (int t = 0; t < 16; t++) {
            int id = t * 256 + tid;
            int p = id >> 11;
            int rem = id & 2047;
            int n = rem >> 3;
            int u = rem & 7;
            const __half* src = Bprep +
                ((size_t)((p * ntiles256 + tileY) * 256 + n)) * Kpad + c * 64 + u * 8;
            uint32_t dst = bBase + (uint32_t)buf * BBUF + (uint32_t)p * BPLANE
                         + (uint32_t)n * AS_STRIDE + u * 16;
            CP_ASYNC16(dst, src);
        }
    };

    auto issueA = [&](int c, int buf) {    // PIPE modes only
        #pragma unroll
        for (int t = 0; t < 8; t++) {
            int id = t * 256 + tid;          // 0..2047
            int p = id >> 10;                // plane
            int rem = id & 1023;
            int n = rem >> 3;                // row 0..127
            int u = rem & 7;
            const __half* src;
            if (AMODE == 5) {
                src = Aprep + (size_t)p * aStride
                    + (size_t)(rowBase + n) * Kpad + c * 64 + u * 8;
            } else {
                int k0 = c * 64;
                int idxr = I1[2 * (rowBase + n) + (k0 >= HDIM)];
                src = Aprep + (size_t)p * aStride
                    + (size_t)idxr * HDIM + (k0 & 255) + u * 8;
            }
            uint32_t dst = aBase + (uint32_t)buf * ABUF + (uint32_t)p * APLANE
                         + (uint32_t)n * AS_STRIDE + u * 16;
            CP_ASYNC16(dst, src);
        }
    };

    auto fillA = [&](int c) {   // non-PIPE: direct LDG + split + STS into buffer 0
        const int k = c * 64 + kk;
        #pragma unroll 8
        for (int v = 0; v < 32; v++) {
            int r = r0 + (v << 2);
            int grow = rowBase + r;
            float val = 0.f;
            if (AMODE == 0) {
                if (k < K) val = A[(size_t)grow * lda + k];
            } else if (AMODE == 2) {
                if (k < AFEAT)      val = X1[(size_t)grow * AFEAT + k];
                else if (k < K)     val = X2[(size_t)grow * HDIM + (k - AFEAT)];
            } else if (AMODE == 3) {
                val = (k < HDIM) ? X1[(size_t)grow * HDIM + k]
                                 : X2[(size_t)grow * HDIM + (k - HDIM)];
            }
            __half p0, p1; split2(val, p0, p1);
            uint32_t so = (uint32_t)r * (AS_STRIDE / 2) + kk;
            ap[so] = p0;
            ap[so + APLANE / 2] = p1;
        }
    };

    const int pa[3] = {0, 0, 1};
    const int pb[3] = {0, 1, 0};

    auto mmaBlock = [&](int buf) {
        #pragma unroll
        for (int j = 0; j < 3; j++) {
            uint32_t ab = aBase + (uint32_t)buf * ABUF + (uint32_t)pa[j] * APLANE;
            uint32_t bb = bBase + (uint32_t)buf * BBUF + (uint32_t)pb[j] * BPLANE;
            #pragma unroll
            for (int ks = 0; ks < 4; ks++) {
                uint32_t af[4][4];
                #pragma unroll
                for (int mi = 0; mi < 4; mi++) ldsm4(af[mi], ab + aoffs[mi] + ks * 32);
                uint32_t bf[4][4];
                #pragma unroll
                for (int njp = 0; njp < 4; njp++) ldsm4(bf[njp], bb + boffs[njp] + ks * 32);
                #pragma unroll
                for (int mi = 0; mi < 4; mi++) {
                    #pragma unroll
                    for (int njp = 0; njp < 4; njp++) {
                        mma16816(acc[mi][2 * njp],     af[mi], bf[njp][0], bf[njp][1]);
                        mma16816(acc[mi][2 * njp + 1], af[mi], bf[njp][2], bf[njp][3]);
                    }
                }
            }
        }
    };

    if (PIPE) {
        issueA(0, 0); issueB(0, 0); CP_COMMIT();
        CP_WAIT0(); __syncthreads();
        for (int c = 0; c < nchunks; c++) {
            const int cur = c & 1, nxt = cur ^ 1;
            const bool hasNext = (c + 1 < nchunks);
            if (hasNext) { issueA(c + 1, nxt); issueB(c + 1, nxt); CP_COMMIT(); }
            mmaBlock(cur);
            if (hasNext) CP_WAIT0();
            __syncthreads();
        }
    } else {
        for (int c = 0; c < nchunks; c++) {
            issueB(c, 0); CP_COMMIT();
            fillA(c);
            CP_WAIT0(); __syncthreads();
            mmaBlock(0);
            __syncthreads();
        }
    }

    // ---- epilogue: fused bias / C-add / relu, direct float2 stores ----
    #pragma unroll
    for (int mi = 0; mi < 4; mi++) {
        int r0g = rowBase + wm * 64 + mi * 16 + (lane >> 2);
        int r1g = r0g + 8;
        #pragma unroll
        for (int nj = 0; nj < 8; nj++) {
            int col = colBase + wn * 64 + nj * 8 + (lane & 3) * 2;
            float v0 = acc[mi][nj][0], v1 = acc[mi][nj][1];
            float v2 = acc[mi][nj][2], v3 = acc[mi][nj][3];
            if (BIAS) {
                float2 b2v = *(const float2*)&bias[col];
                v0 += b2v.x; v1 += b2v.y; v2 += b2v.x; v3 += b2v.y;
            }
            if (ADDC) {
                float2 c0 = *(const float2*)&Cadd[(size_t)r0g * Nfull + col];
                float2 c1 = *(const float2*)&Cadd[(size_t)r1g * Nfull + col];
                v0 += c0.x; v1 += c0.y; v2 += c1.x; v3 += c1.y;
            }
            if (RELU) {
                v0 = fmaxf(v0, 0.f); v1 = fmaxf(v1, 0.f);
                v2 = fmaxf(v2, 0.f); v3 = fmaxf(v3, 0.f);
            }
            float2 w0 = make_float2(v0, v1), w1 = make_float2(v2, v3);
            *(float2*)&C[(size_t)r0g * Nfull + col] = w0;
            *(float2*)&C[(size_t)r1g * Nfull + col] = w1;
        }
    }
}

template<int AM, bool BI, bool RE, bool AD>
static inline void tgemm(const float* A, int lda, const __half* Bp,
                         const float* bias, const float* Cadd, float* C,
                         int M, int Nfull, int K, int Kpad,
                         const float* X1 = nullptr, const float* X2 = nullptr,
                         const int* I1 = nullptr, const int* I2 = nullptr,
                         const __half* Aprep = nullptr, size_t aStride = 0) {
    cudaFuncSetAttribute(tgemm_k<AM, BI, RE, AD>,
                         cudaFuncAttributeMaxDynamicSharedMemorySize, SMEM_PIPE);
    int smem = (AM >= 5) ? SMEM_PIPE : SMEM_SINGLE;
    dim3 grid(M / 128, Nfull / 256);
    tgemm_k<AM, BI, RE, AD><<<grid, 256, smem>>>(
        A, lda, Bp, Nfull / 256, Aprep, aStride, bias, Cadd, C, Nfull, K, Kpad,
        X1, X2, I1, I2);
}

// ---------------- fp32 SIMT GEMM (small heads only) ----------------
template<bool BIAS, bool RELU, int OUTMODE>
__global__ __launch_bounds__(256, 2)
void gemm_k(const float* __restrict__ A, int lda,
            const float* __restrict__ B,
            const float* __restrict__ bias,
            float* __restrict__ C,
            int M, int N, int K)
{
    __shared__ float As[16][128];
    __shared__ float Bs[16][128];

    const int tid = threadIdx.x;
    const int ty = tid >> 4, tx = tid & 15;
    const int rowBase = blockIdx.x * 128;
    const int colBase = blockIdx.y * 128;
    const int lm = tid & 127;
    const int lk = tid >> 7;
    const int arow = rowBase + lm;
    const float* pA = A + (size_t)arow * lda;

    float acc[8][8];
    #pragma unroll
    for (int i = 0; i < 8; i++)
        #pragma unroll
        for (int j = 0; j < 8; j++) acc[i][j] = 0.f;

    for (int k0 = 0; k0 < K; k0 += 16) {
        #pragma unroll
        for (int jj = 0; jj < 8; jj++) {
            int kk2 = lk + 2 * jj;
            int kg = k0 + kk2;
            As[kk2][lm] = (kg < K) ? pA[kg] : 0.f;
        }
        {
            int ng = colBase + lm;
            #pragma unroll
            for (int jj = 0; jj < 8; jj++) {
                int kk2 = lk + 2 * jj;
                int kg = k0 + kk2;
                float val = 0.f;
                if (kg < K && ng < N) val = B[(size_t)kg * N + ng];
                Bs[kk2][lm] = val;
            }
        }
        __syncthreads();
        #pragma unroll
        for (int kk2 = 0; kk2 < 16; kk2++) {
            const float4* apx = reinterpret_cast<const float4*>(&As[kk2][ty * 8]);
            const float4* bpx = reinterpret_cast<const float4*>(&Bs[kk2][tx * 8]);
            float4 a0 = apx[0], a1 = apx[1];
            float4 b0 = bpx[0], b1 = bpx[1];
            float a[8], b[8];
            a[0] = a0.x; a[1] = a0.y; a[2] = a0.z; a[3] = a0.w;
            a[4] = a1.x; a[5] = a1.y; a[6] = a1.z; a[7] = a1.w;
            b[0] = b0.x; b[1] = b0.y; b[2] = b0.z; b[3] = b0.w;
            b[4] = b1.x; b[5] = b1.y; b[6] = b1.z; b[7] = b1.w;
            #pragma unroll
            for (int i = 0; i < 8; i++)
                #pragma unroll
                for (int j = 0; j < 8; j++)
                    acc[i][j] += a[i] * b[j];
        }
        __syncthreads();
    }

    #pragma unroll
    for (int i = 0; i < 8; i++) {
        int r = rowBase + ty * 8 + i;
        #pragma unroll
        for (int j = 0; j < 8; j++) {
            int n = colBase + tx * 8 + j;
            float val = acc[i][j];
            if (BIAS) val += (n < N) ? bias[n] : 0.f;
            if (RELU) val = fmaxf(val, 0.f);
            if (OUTMODE == 0) {
                C[(size_t)r * N + n] = val;
            } else if (n < N) {
                size_t o;
                if (OUTMODE == 1)
                    o = (size_t)(r >> 6) * OUTCOLS + BOND_BLOCK + (size_t)(r & 63) * AOUT + n;
                else
                    o = (size_t)(r >> 7) * OUTCOLS + (size_t)(r & 127) * BOUT + n;
                C[o] = val;
            }
        }
    }
}

template<bool BI, bool RE, int OM>
static inline void gemm32(const float* A, int lda, const float* B, const float* bias,
                          float* C, int M, int N, int K) {
    dim3 grid(M / 128, (N + 127) / 128);
    gemm_k<BI, RE, OM><<<grid, 256>>>(A, lda, B, bias, C, M, N, K);
}

// ---------------- per-(molecule, head) attention ----------------
__global__ __launch_bounds__(64)
void attn_k(const float* __restrict__ q, const float* __restrict__ k,
            const float* __restrict__ v, float* __restrict__ ctx)
{
    __shared__ float Qs[64][32], Ks[64][32], Vs[64][32];
    __shared__ float Ss[64][65];

    int mol  = blockIdx.x >> 3;
    int head = blockIdx.x & 7;
    int t = threadIdx.x;
    size_t rbase = ((size_t)mol * APER + t) * HDIM + head * DKH;

    #pragma unroll
    for (int c = 0; c < 32; c += 4) {
        *(float4*)&Qs[t][c] = *(const float4*)&q[rbase + c];
        *(float4*)&Ks[t][c] = *(const float4*)&k[rbase + c];
        *(float4*)&Vs[t][c] = *(const float4*)&v[rbase + c];
    }
    __syncthreads();

    float qr[32];
    #pragma unroll
    for (int c = 0; c < 32; c++) qr[c] = Qs[t][c];

    const float scale = 0.17677669529663687f;
    float mx = -1e30f;
    for (int j = 0; j < 64; j++) {
        float d = 0.f;
        #pragma unroll
        for (int c = 0; c < 32; c++) d += qr[c] * Ks[j][c];
        d *= scale;
        Ss[t][j] = d;
        mx = fmaxf(mx, d);
    }
    float sum = 0.f;
    for (int j = 0; j < 64; j++) {
        float e = expf(Ss[t][j] - mx);
        Ss[t][j] = e;
        sum += e;
    }
    float inv = 1.f / sum;

    float o[32];
    #pragma unroll
    for (int c = 0; c < 32; c++) o[c] = 0.f;
    for (int j = 0; j < 64; j++) {
        float sj = Ss[t][j];
        #pragma unroll
        for (int c = 0; c < 32; c++) o[c] += sj * Vs[j][c];
    }
    #pragma unroll
    for (int c = 0; c < 32; c += 4) {
        float4 w = make_float4(o[c] * inv, o[c + 1] * inv, o[c + 2] * inv, o[c + 3] * inv);
        *(float4*)&ctx[rbase + c] = w;
    }
}

// ---------------- graph vector + final graph projection ----------------
__global__ void gvec_k(const float* __restrict__ af, float* __restrict__ gv) {
    int mol = blockIdx.x;
    int c = threadIdx.x;
    const float* p = af + (size_t)mol * APER * HDIM + c;
    float s = 0.f;
    #pragma unroll 8
    for (int i = 0; i < APER; i++) s += p[(size_t)i * HDIM];
    gv[mol * HDIM + c] = s;
}

__global__ void gout_k(const float* __restrict__ ghid, const float* __restrict__ G2,
                       const float* __restrict__ g2, float* __restrict__ out) {
    int m = blockIdx.x * blockDim.x + threadIdx.x;
    if (m < BMOL) {
        float s = g2[0];
        const float* p = ghid + (size_t)m * MLPD;
        #pragma unroll 8
        for (int kk = 0; kk < MLPD; kk++) s += p[kk] * G2[kk];
        out[(size_t)m * OUTCOLS + (OUTCOLS - 1)] = s;
    }
}

// ---------------- launcher ----------------
extern "C" void kernel_launch(void* const* d_in, const int* in_sizes, int n_in,
                              void* d_out, int out_size) {
    (void)in_sizes; (void)n_in; (void)out_size;

    const float* f_atoms    = (const float*)d_in[0];
    const float* f_bonds    = (const float*)d_in[1];
    const float* prev_hid   = (const float*)d_in[2];
    const int*   b2a        = (const int*)d_in[3];
    const int*   b2t        = (const int*)d_in[4];
    const int*   b2rev      = (const int*)d_in[5];
    const int*   bond_pairs = (const int*)d_in[6];
    const float* W_i   = (const float*)d_in[7];
    const float* W_h   = (const float*)d_in[8];
    const float* W_o   = (const float*)d_in[9];
    const float* b_o   = (const float*)d_in[10];
    const float* Wq    = (const float*)d_in[11];
    const float* Wk    = (const float*)d_in[12];
    const float* Wv    = (const float*)d_in[13];
    const float* Wattn = (const float*)d_in[14];
    const float* W_vv  = (const float*)d_in[15];
    const float* W_vc  = (const float*)d_in[16];
    const float* A1    = (const float*)d_in[17];
    const float* a1    = (const float*)d_in[18];
    const float* A2    = (const float*)d_in[19];
    const float* a2    = (const float*)d_in[20];
    const float* B1    = (const float*)d_in[21];
    const float* b1    = (const float*)d_in[22];
    const float* B2    = (const float*)d_in[23];
    const float* b2b   = (const float*)d_in[24];
    const float* G1    = (const float*)d_in[25];
    const float* g1    = (const float*)d_in[26];
    const float* G2    = (const float*)d_in[27];
    const float* g2    = (const float*)d_in[28];
    float* out = (float*)d_out;

    float *h0, *hA, *hB, *asum, *afeats, *qp, *kp, *vp, *ctx, *att, *atomf;
    float *ahid, *bhid, *gvec, *ghid;
    __half *bprep, *msgP, *afP, *atfP;
    void* p;
    cudaGetSymbolAddress(&p, g_h0);     h0     = (float*)p;
    cudaGetSymbolAddress(&p, g_hA);     hA     = (float*)p;
    cudaGetSymbolAddress(&p, g_hB);     hB     = (float*)p;
    cudaGetSymbolAddress(&p, g_asum);   asum   = (float*)p;
    cudaGetSymbolAddress(&p, g_afeats); afeats = (float*)p;
    cudaGetSymbolAddress(&p, g_q);      qp     = (float*)p;
    cudaGetSymbolAddress(&p, g_k);      kp     = (float*)p;
    cudaGetSymbolAddress(&p, g_v);      vp     = (float*)p;
    cudaGetSymbolAddress(&p, g_ctx);    ctx    = (float*)p;
    cudaGetSymbolAddress(&p, g_att);    att    = (float*)p;
    cudaGetSymbolAddress(&p, g_atomf);  atomf  = (float*)p;
    cudaGetSymbolAddress(&p, g_ahid);   ahid   = (float*)p;
    cudaGetSymbolAddress(&p, g_bhid);   bhid   = (float*)p;
    cudaGetSymbolAddress(&p, g_gvec);   gvec   = (float*)p;
    cudaGetSymbolAddress(&p, g_ghid);   ghid   = (float*)p;
    cudaGetSymbolAddress(&p, g_bprep);  bprep  = (__half*)p;
    cudaGetSymbolAddress(&p, g_msgP);   msgP   = (__half*)p;
    cudaGetSymbolAddress(&p, g_afP);    afP    = (__half*)p;
    cudaGetSymbolAddress(&p, g_atfP);   atfP   = (__half*)p;

    // ---- weight split/transpose prep ----
    auto prepN = [&](const float* W, int Kw, int Nw, int Kpad, size_t off) {
        int total = (Nw >> 8) * 256 * Kpad;
        prep_normal_k<<<(total + 255) / 256, 256>>>(W, Kw, Nw, Kpad, bprep + off);
    };
    prepN(W_i,   111, 256, 128, OFF_WI);
    prepN(W_h,   256, 256, 256, OFF_WH);
    prepN(W_o,   354, 256, 384, OFF_WO);
    prepN(Wq,    256, 256, 256, OFF_WQ);
    prepN(Wk,    256, 256, 256, OFF_WK);
    prepN(Wv,    256, 256, 256, OFF_WV);
    prepN(Wattn, 256, 256, 256, OFF_WATTN);
    prep_vvvc_k<<<(256 * 512 + 255) / 256, 256>>>(W_vv, W_vc, bprep + OFF_VVVC);
    prepN(A1,    256, 512, 256, OFF_A1);
    prepN(B1,    512, 512, 512, OFF_B1);

    // ---- inverse edge index ----
    inv_zero_k<<<NATOMS / 256, 256>>>();
    inv_build_k<<<NDIR / 256, 256>>>(b2t);
    inv_sort_k<<<NATOMS / 256, 256>>>();

    const size_t msgStride = (size_t)NDIR * HDIM;
    const size_t atStride  = (size_t)NATOMS * HDIM;

    // ---- h0 = relu(f_bonds @ W_i) ----
    tgemm<0, false, true, false>(f_bonds, BFEAT, bprep + OFF_WI, nullptr, nullptr,
                                 h0, NDIR, 256, 111, 128);

    // ---- DMPNN loop: segsum -> message split planes -> pipelined GEMM ----
    const float* hcur = h0;
    for (int it = 0; it < DEPTH - 1; ++it) {
        float* dst = (it & 1) ? hB : hA;
        segsum_k<<<(NATOMS * (HDIM / 4)) / 256, 256>>>(hcur, asum);
        amsg_split_k<<<(NDIR * 64) / 256, 256>>>(asum, hcur, b2a, b2rev, msgP);
        tgemm<5, false, true, true>(nullptr, 0, bprep + OFF_WH, nullptr, h0, dst,
                                    NDIR, 256, 256, 256, nullptr, nullptr, nullptr, nullptr,
                                    msgP, msgStride);
        hcur = dst;
    }

    // ---- atom features ----
    segsum_k<<<(NATOMS * (HDIM / 4)) / 256, 256>>>(hcur, asum);
    tgemm<2, true, true, false>(nullptr, 0, bprep + OFF_WO, b_o, nullptr, afeats,
                                NATOMS, 256, 354, 384, f_atoms, asum);
    split_mat_k<<<(NATOMS * 64) / 256, 256>>>(afeats, afP, NATOMS);

    // ---- attention ----
    tgemm<5, false, false, false>(nullptr, 0, bprep + OFF_WQ, nullptr, nullptr, qp,
                                  NATOMS, 256, 256, 256, nullptr, nullptr, nullptr, nullptr,
                                  afP, atStride);
    tgemm<5, false, false, false>(nullptr, 0, bprep + OFF_WK, nullptr, nullptr, kp,
                                  NATOMS, 256, 256, 256, nullptr, nullptr, nullptr, nullptr,
                                  afP, atStride);
    tgemm<5, false, false, false>(nullptr, 0, bprep + OFF_WV, nullptr, nullptr, vp,
                                  NATOMS, 256, 256, 256, nullptr, nullptr, nullptr, nullptr,
                                  afP, atStride);
    attn_k<<<BMOL * NHEADS, 64>>>(qp, kp, vp, ctx);
    tgemm<0, false, false, true>(ctx, 256, bprep + OFF_WATTN, nullptr, afeats, att,
                                 NATOMS, 256, 256, 256);

    // ---- atom_feats = relu(prev_hid @ Wvv.T + att @ Wvc.T) ----
    tgemm<3, false, true, false>(nullptr, 0, bprep + OFF_VVVC, nullptr, nullptr, atomf,
                                 NATOMS, 256, 512, 512, prev_hid, att);
    split_mat_k<<<(NATOMS * 64) / 256, 256>>>(atomf, atfP, NATOMS);

    // ---- atom head ----
    tgemm<5, true, true, false>(nullptr, 0, bprep + OFF_A1, a1, nullptr, ahid,
                                NATOMS, 512, 256, 256, nullptr, nullptr, nullptr, nullptr,
                                atfP, atStride);
    gemm32<true, false, 1>(ahid, MLPD, A2, a2, out, NATOMS, AOUT, MLPD);

    // ---- bond head (gathered pre-split atomf planes) ----
    tgemm<6, true, true, false>(nullptr, 0, bprep + OFF_B1, b1, nullptr, bhid,
                                NUND, 512, 512, 512, nullptr, nullptr, bond_pairs, nullptr,
                                atfP, atStride);
    gemm32<true, false, 2>(bhid, MLPD, B2, b2b, out, NUND, BOUT, MLPD);

    // ---- graph head ----
    gvec_k<<<BMOL, HDIM>>>(atomf, gvec);
    gemm32<true, true, 0>(gvec, HDIM, G1, g1, ghid, BMOL, MLPD, HDIM);
    gout_k<<<(BMOL + 255) / 256, 256>>>(ghid, G2, g2, out);
}